// round 7
// baseline (speedup 1.0000x reference)
#include <cuda_runtime.h>
#include <cuda_bf16.h>
#include <cstddef>
#include <cstdint>

#define NN   64
#define CIN  192
#define TT   256
#define VV   25
#define KK   3
#define COUT 64
#define SS   5
#define OC   192
#define MM   6400
#define TCH  8
#define MB   200
#define NTC  32
#define NTHR 384
#define SYP  202

// ---------------- scratch globals -------------------------------------------
__device__ __align__(16) uint4 g_Wfrag[2 * 12 * 12 * 32];         // [split][ot][k16][lane]
__device__ __align__(16) float g_pt[(size_t)NN * NTC * OC * VV];
__device__ __align__(16) float g_ybar[NN * OC * VV];

// ---------------- helpers ----------------------------------------------------
__device__ __forceinline__ float2 ffma2(float2 a, float2 b, float2 c) {
    float2 d;
    asm("fma.rn.f32x2 %0, %1, %2, %3;"
        : "=l"(reinterpret_cast<unsigned long long&>(d))
        : "l"(reinterpret_cast<unsigned long long const&>(a)),
          "l"(reinterpret_cast<unsigned long long const&>(b)),
          "l"(reinterpret_cast<unsigned long long const&>(c)));
    return d;
}
__device__ __forceinline__ void cpasync16(uint32_t dst, const void* src) {
    asm volatile("cp.async.cg.shared.global [%0], [%1], 16;" :: "r"(dst), "l"(src));
}
__device__ __forceinline__ void cpcommit() { asm volatile("cp.async.commit_group;"); }
template<int N> __device__ __forceinline__ void cpwait() {
    asm volatile("cp.async.wait_group %0;" :: "n"(N));
}
__device__ __forceinline__ uint32_t smem_u32(const void* p) {
    uint32_t a;
    asm("{ .reg .u64 t; cvta.to.shared.u64 t, %1; cvt.u32.u64 %0, t; }" : "=r"(a) : "l"(p));
    return a;
}
#define MMA(acr, A0, A1, A2, A3, B0, B1) \
    asm volatile("mma.sync.aligned.m16n8k16.row.col.f32.bf16.bf16.f32 " \
        "{%0,%1,%2,%3}, {%4,%5,%6,%7}, {%8,%9}, {%0,%1,%2,%3};" \
        : "+f"((acr)[0]), "+f"((acr)[1]), "+f"((acr)[2]), "+f"((acr)[3]) \
        : "r"(A0), "r"(A1), "r"(A2), "r"(A3), "r"(B0), "r"(B1))

// smem byte layout
#define OFF_BC    0                         // 192 floats
#define OFF_SA    768                       // [3][25][28] floats = 8400 B
#define OFF_STG   9216                      // 2 x (32*204*4 = 26112)
#define STG_SET   26112
#define OFF_XH    61440                     // 16*200 words = 12800 B
#define OFF_XL    74240
#define OFF_SY    9216                      // union; 192*202*4 = 155136
#define SMEM_BYTES 164352

// ============================================================================
// W fragment precompute: per (split, warp-row-tile, k16-step, lane) -> uint4
// ============================================================================
__global__ void k_wfrag(const float* __restrict__ Wc) {
    int gid = blockIdx.x * 256 + threadIdx.x;
    if (gid >= 288 * 32) return;
    int lane = gid & 31, warp = gid >> 5;
    int s = warp / 144, rem = warp % 144, ot = rem / 12, kk = rem % 12;
    int g = lane >> 2, tg = lane & 3;
    int r0 = ot * 16 + g, k0 = kk * 16 + 2 * tg;
    uint32_t v[4];
#pragma unroll
    for (int i = 0; i < 4; i++) {
        int r = r0 + (i & 1) * 8;
        int c = k0 + (i >> 1) * 8;
        float f0 = Wc[r * CIN + c], f1 = Wc[r * CIN + c + 1];
        if (s) {
            f0 -= __bfloat162float(__float2bfloat16(f0));
            f1 -= __bfloat162float(__float2bfloat16(f1));
        }
        __nv_bfloat162 p(__float2bfloat16(f0), __float2bfloat16(f1));
        v[i] = *(uint32_t*)&p;
    }
    g_Wfrag[warp * 32 + lane] = make_uint4(v[0], v[1], v[2], v[3]);
}

// ============================================================================
// main: bf16-split mma.sync GEMM (regs) -> sY -> ybar + contraction + out
// grid (NTC, NN), 384 threads, 1 CTA/SM
// ============================================================================
__global__ __launch_bounds__(NTHR)
void k_main(const float* __restrict__ x, const float* __restrict__ bc,
            const float* __restrict__ A, float* __restrict__ out) {
    extern __shared__ __align__(16) char smem[];
    const uint32_t sb = smem_u32(smem);
    float* sbc = (float*)(smem + OFF_BC);
    float* sA  = (float*)(smem + OFF_SA);
    float* sY  = (float*)(smem + OFF_SY);
    uint32_t* sXh = (uint32_t*)(smem + OFF_XH);
    uint32_t* sXl = (uint32_t*)(smem + OFF_XL);

    const int tid = threadIdx.x, wid = tid >> 5, lane = tid & 31;
    const int g = lane >> 2, tg = lane & 3;
    const int tcb = blockIdx.x, n = blockIdx.y;
    const float* xn = x + (size_t)n * CIN * MM + (size_t)tcb * MB;

    for (int i = tid; i < OC; i += NTHR) sbc[i] = bc[i];
    for (int i = tid; i < KK * VV * VV; i += NTHR) {
        int k = i / (VV * VV), r = i % (VV * VV);
        sA[(k * VV + r / VV) * 28 + (r % VV)] = A[i];
    }

    auto loadX = [&](int b, int kc) {
        const float* src0 = xn + (size_t)kc * 32 * MM;
        for (int i = tid; i < 1600; i += NTHR) {
            int row = i / 50, j = i % 50;
            cpasync16(sb + OFF_STG + b * STG_SET + (row * 204 + j * 4) * 4,
                      src0 + (size_t)row * MM + j * 4);
        }
        cpcommit();
    };
    loadX(0, 0);
    __syncthreads();

    const int r0 = wid * 16 + g, r1 = r0 + 8;
    float acc[25][4];
    {
        const float bv0 = sbc[r0], bv1 = sbc[r1];
#pragma unroll
        for (int nt = 0; nt < 25; nt++) {
            acc[nt][0] = bv0; acc[nt][1] = bv0;
            acc[nt][2] = bv1; acc[nt][3] = bv1;
        }
    }

    for (int kc = 0; kc < 6; kc++) {
        const int b = kc & 1;
        if (kc < 5) { loadX(b ^ 1, kc + 1); cpwait<1>(); }
        else        { cpwait<0>(); }
        __syncthreads();   // stage[b] arrived; prior mma done -> sX reusable

        // prefetch W frags for this chunk's two k16 steps
        uint4 ah[2], al[2];
#pragma unroll
        for (int s = 0; s < 2; s++) {
            const int kk = kc * 2 + s;
            ah[s] = g_Wfrag[((0 * 12 + wid) * 12 + kk) * 32 + lane];
            al[s] = g_Wfrag[((1 * 12 + wid) * 12 + kk) * 32 + lane];
        }

        // convert fp32 stage -> bf16 hi/lo k-pair words [kp][m]
        const float* sF = (const float*)(smem + OFF_STG + b * STG_SET);
        for (int i = tid; i < 3200; i += NTHR) {
            const int m = i % 200, kp = i / 200;
            const float f0 = sF[(2 * kp) * 204 + m];
            const float f1 = sF[(2 * kp + 1) * 204 + m];
            const __nv_bfloat16 h0 = __float2bfloat16(f0);
            const __nv_bfloat16 h1 = __float2bfloat16(f1);
            const __nv_bfloat16 l0 = __float2bfloat16(f0 - __bfloat162float(h0));
            const __nv_bfloat16 l1 = __float2bfloat16(f1 - __bfloat162float(h1));
            __nv_bfloat162 hp(h0, h1), lp(l0, l1);
            sXh[kp * 200 + m] = *(uint32_t*)&hp;
            sXl[kp * 200 + m] = *(uint32_t*)&lp;
        }
        __syncthreads();

#pragma unroll
        for (int s = 0; s < 2; s++) {
            const uint32_t* bhp = sXh + (8 * s + tg) * 200 + g;
            const uint32_t* blp = sXl + (8 * s + tg) * 200 + g;
            const uint32_t a0h = ah[s].x, a1h = ah[s].y, a2h = ah[s].z, a3h = ah[s].w;
            const uint32_t a0l = al[s].x, a1l = al[s].y, a2l = al[s].z, a3l = al[s].w;
#pragma unroll
            for (int ntg = 0; ntg < 5; ntg++) {
                uint32_t b0h[5], b1h[5], b0l[5], b1l[5];
#pragma unroll
                for (int q = 0; q < 5; q++) {
                    const int o8 = (ntg * 5 + q) * 8;
                    b0h[q] = bhp[o8]; b1h[q] = bhp[800 + o8];
                    b0l[q] = blp[o8]; b1l[q] = blp[800 + o8];
                }
#pragma unroll
                for (int q = 0; q < 5; q++) MMA(acc[ntg * 5 + q], a0h, a1h, a2h, a3h, b0h[q], b1h[q]);
#pragma unroll
                for (int q = 0; q < 5; q++) MMA(acc[ntg * 5 + q], a0l, a1l, a2l, a3l, b0h[q], b1h[q]);
#pragma unroll
                for (int q = 0; q < 5; q++) MMA(acc[ntg * 5 + q], a0h, a1h, a2h, a3h, b0l[q], b1l[q]);
            }
        }
    }
    __syncthreads();   // all mma done; operand smem dead -> sY region free

    // ---- accumulators -> sY ----
#pragma unroll
    for (int nt = 0; nt < 25; nt++) {
        const int cc = nt * 8 + 2 * tg;
        *(float2*)&sY[r0 * SYP + cc] = make_float2(acc[nt][0], acc[nt][1]);
        *(float2*)&sY[r1 * SYP + cc] = make_float2(acc[nt][2], acc[nt][3]);
    }
    __syncthreads();

    // ---- ybar t-partials ----
    {
        float* pt = g_pt + ((size_t)n * NTC + tcb) * (OC * VV);
        for (int idx = tid; idx < OC * VV; idx += NTHR) {
            int o = idx / VV, v = idx % VV;
            const float* yr = &sY[o * SYP + v];
            float s = 0.f;
#pragma unroll
            for (int t = 0; t < TCH; t++) s += yr[t * VV];
            pt[idx] = s;
        }
    }

    // ---- graph contraction: 512 pairs (pair = c*8 + t) ----
    float2 accO[2][12];
    float  accL[2] = {0.f, 0.f};
#pragma unroll
    for (int pp = 0; pp < 2; pp++)
#pragma unroll
        for (int j = 0; j < 12; j++) accO[pp][j] = make_float2(0.f, 0.f);

#pragma unroll
    for (int pp = 0; pp < 2; pp++) {
        const int pair = tid + pp * NTHR;
        if (pair >= COUT * TCH) break;
        const int cof = (pair & 7) * VV;
#pragma unroll
        for (int k = 0; k < KK; k++) {
            const int row = (pair >> 3) + k * COUT;
#pragma unroll
            for (int v = 0; v < VV; v++) {
                const float4* ap = (const float4*)&sA[(k * VV + v) * 28];
                const float4 a0 = ap[0], a1 = ap[1], a2 = ap[2],
                             a3 = ap[3], a4 = ap[4], a5 = ap[5];
                const float  aL = sA[(k * VV + v) * 28 + 24];
                const float y = sY[row * SYP + cof + v];
                const float2 yy = make_float2(y, y);
                const float2 af[12] = {
                    {a0.x,a0.y},{a0.z,a0.w},{a1.x,a1.y},{a1.z,a1.w},
                    {a2.x,a2.y},{a2.z,a2.w},{a3.x,a3.y},{a3.z,a3.w},
                    {a4.x,a4.y},{a4.z,a4.w},{a5.x,a5.y},{a5.z,a5.w}};
#pragma unroll
                for (int j = 0; j < 12; j++) accO[pp][j] = ffma2(af[j], yy, accO[pp][j]);
                accL[pp] += y * aL;
            }
        }
    }
    __syncthreads();

#pragma unroll
    for (int pp = 0; pp < 2; pp++) {
        const int pair = tid + pp * NTHR;
        if (pair < COUT * TCH) {
            float* st = &sY[pair * VV];
#pragma unroll
            for (int j = 0; j < 12; j++) { st[2*j] = accO[pp][j].x; st[2*j+1] = accO[pp][j].y; }
            st[24] = accL[pp];
        }
    }
    __syncthreads();

    float* ob = out + (size_t)n * COUT * MM + (size_t)tcb * MB;
    for (int i = tid; i < COUT * MB; i += NTHR) {
        int c = i / MB, j = i % MB;
        ob[(size_t)c * MM + j] = sY[i];
    }
}

// ============================================================================
__global__ __launch_bounds__(256)
void k_ybar_reduce() {
    const int n = blockIdx.x;
    for (int idx = threadIdx.x; idx < OC * VV; idx += 256) {
        float s = 0.f;
#pragma unroll 4
        for (int tc = 0; tc < NTC; tc++)
            s += g_pt[((size_t)n * NTC + tc) * (OC * VV) + idx];
        g_ybar[(size_t)n * OC * VV + idx] = s * (1.f / TT);
    }
}

// ============================================================================
__global__ __launch_bounds__(256)
void k_graphs(const float* __restrict__ W1, const float* __restrict__ b1,
              const float* __restrict__ W2, const float* __restrict__ b2,
              const int* __restrict__ node_type, float* __restrict__ gout) {
    const int n = blockIdx.x, s = blockIdx.y;
    const int tid = threadIdx.x;
    const int slice = tid & 3, o2i = tid >> 2;
    const int o2 = s * COUT + o2i;

    __shared__ float syb[OC * VV];
    __shared__ int   stype[VV];
    {
        const float4* src = (const float4*)(g_ybar + (size_t)n * OC * VV);
        float4* dst = (float4*)syb;
        for (int i = tid; i < OC * VV / 4; i += 256) dst[i] = src[i];
    }
    const bool is64 = (node_type[1] == 0);
    if (tid < VV) stype[tid] = is64 ? node_type[2 * tid] : node_type[tid];
    __syncthreads();

    float x1[VV], x2[VV];
#pragma unroll
    for (int v = 0; v < VV; v++) { x1[v] = 0.f; x2[v] = 0.f; }
    const float* w1r = W1 + (size_t)o2 * OC + slice * 48;
    const float* w2r = W2 + (size_t)o2 * OC + slice * 48;
    const float* yb0 = &syb[slice * 48 * VV];
#pragma unroll 4
    for (int o = 0; o < 48; o++) {
        const float w1 = w1r[o], w2 = w2r[o];
        const float* yb = yb0 + o * VV;
#pragma unroll
        for (int v = 0; v < VV; v++) { x1[v] += w1 * yb[v]; x2[v] += w2 * yb[v]; }
    }
#pragma unroll
    for (int v = 0; v < VV; v++) {
        x1[v] += __shfl_xor_sync(0xffffffffu, x1[v], 1);
        x1[v] += __shfl_xor_sync(0xffffffffu, x1[v], 2);
        x2[v] += __shfl_xor_sync(0xffffffffu, x2[v], 1);
        x2[v] += __shfl_xor_sync(0xffffffffu, x2[v], 2);
    }
    if (slice == 0) {
        const float bb1 = b1[o2], bb2 = b2[o2];
        int cnt = 0; float sem = 0.f;
#pragma unroll
        for (int v = 0; v < VV; v++)
            if (stype[v] == s) { sem += x1[v] + bb1; cnt++; }
        sem *= (1.f / (float)cnt);
        float* gp = gout + (size_t)n * (SS * COUT * VV) + (size_t)o2 * VV;
#pragma unroll
        for (int v = 0; v < VV; v++) gp[v] = sem - (x2[v] + bb2);
    }
}

__global__ void k_copyA(const float* __restrict__ A, float* __restrict__ dst) {
    int i = blockIdx.x * 256 + threadIdx.x;
    if (i < KK * VV * VV) dst[i] = A[i];
}

// ============================================================================
extern "C" void kernel_launch(void* const* d_in, const int* in_sizes, int n_in,
                              void* d_out, int out_size) {
    (void)in_sizes; (void)n_in; (void)out_size;
    const float* x  = (const float*)d_in[0];
    const float* A  = (const float*)d_in[1];
    const int*   nt = (const int*)  d_in[2];
    const float* Wc = (const float*)d_in[3];
    const float* bc = (const float*)d_in[4];
    const float* W1 = (const float*)d_in[5];
    const float* b1 = (const float*)d_in[6];
    const float* W2 = (const float*)d_in[7];
    const float* b2 = (const float*)d_in[8];

    float* out  = (float*)d_out;
    float* outA = out + (size_t)NN * COUT * TT * VV;
    float* outG = outA + KK * VV * VV;

    static int init = 0;
    if (!init) {
        cudaFuncSetAttribute(k_main, cudaFuncAttributeMaxDynamicSharedMemorySize, SMEM_BYTES);
        init = 1;
    }

    k_wfrag      <<<36, 256>>>(Wc);
    k_main       <<<dim3(NTC, NN), NTHR, SMEM_BYTES>>>(x, bc, A, out);
    k_ybar_reduce<<<NN, 256>>>();
    k_graphs     <<<dim3(NN, SS), 256>>>(W1, b1, W2, b2, nt, outG);
    k_copyA      <<<8, 256>>>(A, outA);
}